// round 8
// baseline (speedup 1.0000x reference)
#include <cuda_runtime.h>
#include <cstdint>

#define CSIZE 8
#define NCLUS 16
#define NCTA  (CSIZE * NCLUS)
#define NT    256
#define RWS   32
#define LSEQ  1000
#define HST   132                 // h row stride in floats (16B-aligned, uniform 2-phase)

// float-index offsets into dynamic smem
#define FO_HT1 0                  // [2][32][HST]
#define FO_HT2 8448               // [2][32][HST]
#define FO_GB  16896              // [4][16][33]
#define FO_BS1 19008              // [4][16]
#define FO_BS2 19072
#define FO_WI1 19136
#define FO_WL  19200              // [128]
#define FO_XS  19328              // [32]
#define SMEM_SZ (19360 * 4)

typedef unsigned long long ull;

__device__ __forceinline__ ull ffma2(ull a, ull b, ull c) {
    ull d;
    asm("fma.rn.f32x2 %0, %1, %2, %3;" : "=l"(d) : "l"(a), "l"(b), "l"(c));
    return d;
}
__device__ __forceinline__ ull mul2(ull a, ull b) {
    ull d;
    asm("mul.rn.f32x2 %0, %1, %2;" : "=l"(d) : "l"(a), "l"(b));
    return d;
}
__device__ __forceinline__ ull add2(ull a, ull b) {
    ull d;
    asm("add.rn.f32x2 %0, %1, %2;" : "=l"(d) : "l"(a), "l"(b));
    return d;
}
__device__ __forceinline__ ull packf2(float lo, float hi) {
    ull d;
    asm("mov.b64 %0, {%1, %2};" : "=l"(d) : "f"(lo), "f"(hi));
    return d;
}
__device__ __forceinline__ float flo(ull v) { return __uint_as_float((unsigned)v); }
__device__ __forceinline__ float fhi(ull v) { return __uint_as_float((unsigned)(v >> 32)); }

__device__ __forceinline__ float tanhx(float v) {
    float r; asm("tanh.approx.f32 %0, %1;" : "=f"(r) : "f"(v)); return r;
}
__device__ __forceinline__ float sigx(float v) { return fmaf(tanhx(0.5f * v), 0.5f, 0.5f); }

__device__ __forceinline__ uint32_t smem_u32(const void* p) {
    uint32_t a;
    asm("{ .reg .u64 t; cvta.to.shared.u64 t, %1; cvt.u32.u64 %0, t; }" : "=r"(a) : "l"(p));
    return a;
}
__device__ __forceinline__ uint32_t ctarank() {
    uint32_t r; asm("mov.u32 %0, %%cluster_ctarank;" : "=r"(r)); return r;
}
__device__ __forceinline__ void st_cluster_f32(uint32_t addr, uint32_t rank, float v) {
    asm volatile("{ .reg .u32 ra; mapa.shared::cluster.u32 ra, %0, %1;"
                 " st.shared::cluster.f32 [ra], %2; }"
                 :: "r"(addr), "r"(rank), "f"(v) : "memory");
}
__device__ __forceinline__ void cl_sync() {
    asm volatile("barrier.cluster.arrive.aligned;" ::: "memory");
    asm volatile("barrier.cluster.wait.aligned;" ::: "memory");
}

#define SHFLX(v, d) __shfl_xor_sync(0xffffffffu, (v), (d))
// exchange-reduce 16 slots over 16 lanes (kh = lane&15); validated mapping
// L_l(s) = bitrev4(s) ^ l; final: lane kh holds logical dot (gate'=kh&1, row=kh>>1)
#define REDUCE16(A) do {                                                       \
    _Pragma("unroll") for (int s_ = 0; s_ < 16; s_ += 2)                       \
        A[s_] = add2(A[s_], SHFLX(A[s_ + 1], 8));                              \
    _Pragma("unroll") for (int s_ = 0; s_ < 16; s_ += 4)                       \
        A[s_] = add2(A[s_], SHFLX(A[s_ + 2], 4));                              \
    _Pragma("unroll") for (int s_ = 0; s_ < 16; s_ += 8)                       \
        A[s_] = add2(A[s_], SHFLX(A[s_ + 4], 2));                              \
    A[0] = add2(A[0], SHFLX(A[8], 1));                                         \
} while (0)

// acc = w[0]*h0 + w[1]*h1 + w[2]*h2 + w[3]*h3   (first-touch: mul)
__device__ __forceinline__ ull dot4(const ull* w, ull h0, ull h1, ull h2, ull h3) {
    ull a = mul2(w[0], h0);
    a = ffma2(w[1], h1, a);
    a = ffma2(w[2], h2, a);
    return ffma2(w[3], h3, a);
}
__device__ __forceinline__ ull dot4a(const ull* w, ull h0, ull h1, ull h2, ull h3, ull a) {
    a = ffma2(w[0], h0, a);
    a = ffma2(w[1], h1, a);
    a = ffma2(w[2], h2, a);
    return ffma2(w[3], h3, a);
}

__global__ void __launch_bounds__(NT, 1) __cluster_dims__(CSIZE, 1, 1)
lstm_r8(const float* __restrict__ x,
        const float* __restrict__ w_ih1, const float* __restrict__ w_hh1,
        const float* __restrict__ b_ih1, const float* __restrict__ b_hh1,
        const float* __restrict__ w_ih2, const float* __restrict__ w_hh2,
        const float* __restrict__ b_ih2, const float* __restrict__ b_hh2,
        const float* __restrict__ w_lin, const float* __restrict__ b_lin,
        float* __restrict__ out)
{
    extern __shared__ char sm[];
    float* SF  = (float*)sm;
    float* HT1 = SF + FO_HT1;
    float* HT2 = SF + FO_HT2;
    float* GB  = SF + FO_GB;
    float* BS1 = SF + FO_BS1;
    float* BS2 = SF + FO_BS2;
    float* WI1 = SF + FO_WI1;
    float* WL  = SF + FO_WL;
    float* XS  = SF + FO_XS;

    const int tid  = threadIdx.x;
    const uint32_t rank = ctarank();
    const int clus = blockIdx.x >> 3;
    const int row0 = clus * RWS;
    const int UB   = rank * 16;

    const int lane = tid & 31;
    const int kh   = lane & 15;     // k-slice 0..15
    const int kh1  = kh >> 1;
    const int ul   = 2 * (tid >> 5) + (lane >> 4);   // unit-local 0..15

    // ---- register-resident weights: [gate][pair] f32x2, loaded once ----
    ull W1[4][4], W2I[4][4], W2H[4][4];
#pragma unroll
    for (int g = 0; g < 4; g++) {
        const int gj = g * 128 + UB + ul;
        const float4* p1 = (const float4*)(w_hh1 + gj * 128);
        const float4* p2 = (const float4*)(w_ih2 + gj * 128);
        const float4* p3 = (const float4*)(w_hh2 + gj * 128);
        float4 a, b;
        a = p1[kh]; b = p1[16 + kh];
        W1[g][0] = packf2(a.x, a.y); W1[g][1] = packf2(a.z, a.w);
        W1[g][2] = packf2(b.x, b.y); W1[g][3] = packf2(b.z, b.w);
        a = p2[kh]; b = p2[16 + kh];
        W2I[g][0] = packf2(a.x, a.y); W2I[g][1] = packf2(a.z, a.w);
        W2I[g][2] = packf2(b.x, b.y); W2I[g][3] = packf2(b.z, b.w);
        a = p3[kh]; b = p3[16 + kh];
        W2H[g][0] = packf2(a.x, a.y); W2H[g][1] = packf2(a.z, a.w);
        W2H[g][2] = packf2(b.x, b.y); W2H[g][3] = packf2(b.z, b.w);
    }
    // gate pre-swap: slots 0..7 use gate (kh&1), slots 8..15 use gate (kh&1)^1
    if (kh & 1) {
#pragma unroll
        for (int j = 0; j < 4; j++) {
            ull t;
            t = W1[0][j];  W1[0][j] = W1[1][j];  W1[1][j] = t;
            t = W1[2][j];  W1[2][j] = W1[3][j];  W1[3][j] = t;
            t = W2I[0][j]; W2I[0][j] = W2I[1][j]; W2I[1][j] = t;
            t = W2I[2][j]; W2I[2][j] = W2I[3][j]; W2I[3][j] = t;
            t = W2H[0][j]; W2H[0][j] = W2H[1][j]; W2H[1][j] = t;
            t = W2H[2][j]; W2H[2][j] = W2H[3][j]; W2H[3][j] = t;
        }
    }

    // ---- smem init ----
    for (int i = tid; i < 64; i += NT) {
        int gj = (i >> 4) * 128 + UB + (i & 15);
        BS1[i] = b_ih1[gj] + b_hh1[gj];
        BS2[i] = b_ih2[gj] + b_hh2[gj];
        WI1[i] = w_ih1[gj];
    }
    for (int i = tid; i < 128; i += NT) WL[i] = w_lin[i];
    for (int i = tid; i < 2 * RWS * HST; i += NT) { HT1[i] = 0.0f; HT2[i] = 0.0f; }

    const float blin = b_lin[0];
    const uint32_t smb = smem_u32(sm);

    // act tasks: (unit, row) = (tid>>5, tid&31) and (+8, same row)
    const int uA = tid >> 5;
    const int rA = tid & 31;
    float c1a = 0.f, c1b = 0.f, c2a = 0.f, c2b = 0.f;

    __syncthreads();
    cl_sync();

    const int ga  = kh & 1;
    const int gb2 = 2 + ga;

    int p = 0;
    for (int t = 0; t < LSEQ; t++) {
        const int np = p ^ 1;
        float xv = 0.0f;
        if (tid < 32) xv = x[(row0 + tid) * LSEQ + t];

        // ======== mv1: gates1 = h1[p] @ Whh1^T ========
        {
            const float* h1p = HT1 + p * (RWS * HST) + 4 * kh;
#pragma unroll 1
            for (int q = 0; q < 4; q++) {
                ull A[16], B[16];
                const float* hb = h1p + q * (8 * HST);
#pragma unroll
                for (int s = 0; s < 8; s++) {
                    const int br = ((s & 1) << 2) | (s & 2) | ((s & 4) >> 2);
                    const float* hr = hb + (br ^ kh1) * HST;
                    float4 va = *(const float4*)(hr);
                    float4 vb = *(const float4*)(hr + 64);
                    ull h0 = packf2(va.x, va.y), h1v = packf2(va.z, va.w);
                    ull h2v = packf2(vb.x, vb.y), h3v = packf2(vb.z, vb.w);
                    A[s]     = dot4(W1[0], h0, h1v, h2v, h3v);
                    A[s + 8] = dot4(W1[1], h0, h1v, h2v, h3v);
                    B[s]     = dot4(W1[2], h0, h1v, h2v, h3v);
                    B[s + 8] = dot4(W1[3], h0, h1v, h2v, h3v);
                }
                REDUCE16(A);
                REDUCE16(B);
                int r = 8 * q + kh1;
                GB[(ga  * 16 + ul) * 33 + r] = flo(A[0]) + fhi(A[0]);
                GB[(gb2 * 16 + ul) * 33 + r] = flo(B[0]) + fhi(B[0]);
            }
        }
        if (tid < 32) XS[tid] = xv;
        __syncthreads();

        // ======== act1 -> broadcast h1[np] to all ranks ========
        {
            float xr = XS[rA];
            float g0 = GB[(0 * 16 + uA) * 33 + rA];
            float g1 = GB[(1 * 16 + uA) * 33 + rA];
            float g2 = GB[(2 * 16 + uA) * 33 + rA];
            float g3 = GB[(3 * 16 + uA) * 33 + rA];
            float iv = sigx (fmaf(WI1[uA],      xr, g0 + BS1[uA]));
            float fv = sigx (fmaf(WI1[16 + uA], xr, g1 + BS1[16 + uA]));
            float gv = tanhx(fmaf(WI1[32 + uA], xr, g2 + BS1[32 + uA]));
            float ov = sigx (fmaf(WI1[48 + uA], xr, g3 + BS1[48 + uA]));
            c1a = fmaf(fv, c1a, iv * gv);
            float hA = ov * tanhx(c1a);

            int uB = uA + 8;
            g0 = GB[(0 * 16 + uB) * 33 + rA];
            g1 = GB[(1 * 16 + uB) * 33 + rA];
            g2 = GB[(2 * 16 + uB) * 33 + rA];
            g3 = GB[(3 * 16 + uB) * 33 + rA];
            iv = sigx (fmaf(WI1[uB],      xr, g0 + BS1[uB]));
            fv = sigx (fmaf(WI1[16 + uB], xr, g1 + BS1[16 + uB]));
            gv = tanhx(fmaf(WI1[32 + uB], xr, g2 + BS1[32 + uB]));
            ov = sigx (fmaf(WI1[48 + uB], xr, g3 + BS1[48 + uB]));
            c1b = fmaf(fv, c1b, iv * gv);
            float hB = ov * tanhx(c1b);

            uint32_t adA = smb + 4u * (FO_HT1 + np * (RWS * HST) + rA * HST + UB + uA);
            uint32_t adB = adA + 4u * 8;
#pragma unroll
            for (int rr = 0; rr < CSIZE; rr++) {
                st_cluster_f32(adA, rr, hA);
                st_cluster_f32(adB, rr, hB);
            }
        }
        cl_sync();   // h1[np] complete cluster-wide; h2[np_prev] stores visible

        // ======== readout of step t-1 (rank 0 only) ========
        if (rank == 0 && t > 0 && tid < 32) {
            float s = blin;
            const float* h2r = HT2 + p * (RWS * HST) + tid * HST;
#pragma unroll 8
            for (int u = 0; u < 128; u++) s = fmaf(h2r[u], WL[u], s);
            out[(row0 + tid) * LSEQ + (t - 1)] = s;
        }

        // ======== mv2: gates2 = h1[np] @ Wih2^T + h2[p] @ Whh2^T ========
        {
            const float* h1n = HT1 + np * (RWS * HST) + 4 * kh;
            const float* h2p = HT2 + p  * (RWS * HST) + 4 * kh;
#pragma unroll 1
            for (int q = 0; q < 4; q++) {
                ull A[16], B[16];
                const float* hb1 = h1n + q * (8 * HST);
                const float* hb2 = h2p + q * (8 * HST);
#pragma unroll
                for (int s = 0; s < 8; s++) {
                    const int br = ((s & 1) << 2) | (s & 2) | ((s & 4) >> 2);
                    const int ro = (br ^ kh1) * HST;
                    float4 va = *(const float4*)(hb1 + ro);
                    float4 vb = *(const float4*)(hb1 + ro + 64);
                    ull h0 = packf2(va.x, va.y), h1v = packf2(va.z, va.w);
                    ull h2v = packf2(vb.x, vb.y), h3v = packf2(vb.z, vb.w);
                    A[s]     = dot4(W2I[0], h0, h1v, h2v, h3v);
                    A[s + 8] = dot4(W2I[1], h0, h1v, h2v, h3v);
                    B[s]     = dot4(W2I[2], h0, h1v, h2v, h3v);
                    B[s + 8] = dot4(W2I[3], h0, h1v, h2v, h3v);
                    va = *(const float4*)(hb2 + ro);
                    vb = *(const float4*)(hb2 + ro + 64);
                    h0 = packf2(va.x, va.y); h1v = packf2(va.z, va.w);
                    h2v = packf2(vb.x, vb.y); h3v = packf2(vb.z, vb.w);
                    A[s]     = dot4a(W2H[0], h0, h1v, h2v, h3v, A[s]);
                    A[s + 8] = dot4a(W2H[1], h0, h1v, h2v, h3v, A[s + 8]);
                    B[s]     = dot4a(W2H[2], h0, h1v, h2v, h3v, B[s]);
                    B[s + 8] = dot4a(W2H[3], h0, h1v, h2v, h3v, B[s + 8]);
                }
                REDUCE16(A);
                REDUCE16(B);
                int r = 8 * q + kh1;
                GB[(ga  * 16 + ul) * 33 + r] = flo(A[0]) + fhi(A[0]);
                GB[(gb2 * 16 + ul) * 33 + r] = flo(B[0]) + fhi(B[0]);
            }
        }
        __syncthreads();

        // ======== act2 -> write h2[np] (double-buffered, no extra barrier) ========
        {
            float g0 = GB[(0 * 16 + uA) * 33 + rA];
            float g1 = GB[(1 * 16 + uA) * 33 + rA];
            float g2 = GB[(2 * 16 + uA) * 33 + rA];
            float g3 = GB[(3 * 16 + uA) * 33 + rA];
            float iv = sigx (g0 + BS2[uA]);
            float fv = sigx (g1 + BS2[16 + uA]);
            float gv = tanhx(g2 + BS2[32 + uA]);
            float ov = sigx (g3 + BS2[48 + uA]);
            c2a = fmaf(fv, c2a, iv * gv);
            float hA = ov * tanhx(c2a);

            int uB = uA + 8;
            g0 = GB[(0 * 16 + uB) * 33 + rA];
            g1 = GB[(1 * 16 + uB) * 33 + rA];
            g2 = GB[(2 * 16 + uB) * 33 + rA];
            g3 = GB[(3 * 16 + uB) * 33 + rA];
            iv = sigx (g0 + BS2[uB]);
            fv = sigx (g1 + BS2[16 + uB]);
            gv = tanhx(g2 + BS2[32 + uB]);
            ov = sigx (g3 + BS2[48 + uB]);
            c2b = fmaf(fv, c2b, iv * gv);
            float hB = ov * tanhx(c2b);

            uint32_t adA = smb + 4u * (FO_HT2 + np * (RWS * HST) + rA * HST + UB + uA);
            uint32_t adB = adA + 4u * 8;
#pragma unroll
            for (int rr = 0; rr < CSIZE; rr++) {
                st_cluster_f32(adA, rr, hA);
                st_cluster_f32(adB, rr, hB);
            }
        }
        __syncthreads();   // protect GB (act2 reads) from next mv1 writes; XS likewise
        p = np;
    }

    // final readout (t = LSEQ-1): h2[p] holds h_{L-1}; ensure stores visible
    cl_sync();
    if (rank == 0 && tid < 32) {
        float s = blin;
        const float* h2r = HT2 + p * (RWS * HST) + tid * HST;
#pragma unroll 8
        for (int u = 0; u < 128; u++) s = fmaf(h2r[u], WL[u], s);
        out[(row0 + tid) * LSEQ + (LSEQ - 1)] = s;
    }
}

extern "C" void kernel_launch(void* const* d_in, const int* in_sizes, int n_in,
                              void* d_out, int out_size) {
    cudaFuncSetAttribute(lstm_r8, cudaFuncAttributeMaxDynamicSharedMemorySize, SMEM_SZ);

    const float* x     = (const float*)d_in[0];
    const float* w_ih1 = (const float*)d_in[1];
    const float* w_hh1 = (const float*)d_in[2];
    const float* b_ih1 = (const float*)d_in[3];
    const float* b_hh1 = (const float*)d_in[4];
    const float* w_ih2 = (const float*)d_in[5];
    const float* w_hh2 = (const float*)d_in[6];
    const float* b_ih2 = (const float*)d_in[7];
    const float* b_hh2 = (const float*)d_in[8];
    const float* w_lin = (const float*)d_in[9];
    const float* b_lin = (const float*)d_in[10];
    float* out = (float*)d_out;

    lstm_r8<<<NCTA, NT, SMEM_SZ>>>(x, w_ih1, w_hh1, b_ih1, b_hh1,
                                   w_ih2, w_hh2, b_ih2, b_hh2,
                                   w_lin, b_lin, out);
}

// round 9
// speedup vs baseline: 1.7294x; 1.7294x over previous
#include <cuda_runtime.h>
#include <cstdint>

#define CSIZE 4
#define NCTA  128
#define NT    256
#define RWS   16
#define LSEQ  1000

// float-index offsets in dynamic SMEM
#define FW1   0          // WT1 [128k][128j]
#define FW2I  16384      // WT2I
#define FW2H  32768      // WT2H
#define FH1D  49152      // h1 dup: [128k][32]  (pairs (h_r,h_r), r=0..15)
#define FH2   53248      // h2:     [128k][16]
#define FGB   55296      // gates:  [16r][132]
#define FBS1  57408      // [4][32]
#define FBS2  57536
#define FWI1  57664
#define FWL   57792      // [128]
#define FXS   57920      // [16]
#define SMEM_SZ (57936 * 4)

typedef unsigned long long ull;

__device__ __forceinline__ ull ffma2(ull a, ull b, ull c) {
    ull d;
    asm("fma.rn.f32x2 %0, %1, %2, %3;" : "=l"(d) : "l"(a), "l"(b), "l"(c));
    return d;
}
__device__ __forceinline__ ull add2(ull a, ull b) {
    ull d;
    asm("add.rn.f32x2 %0, %1, %2;" : "=l"(d) : "l"(a), "l"(b));
    return d;
}
__device__ __forceinline__ ull repf(float v) {
    ull d;
    asm("mov.b64 %0, {%1, %1};" : "=l"(d) : "f"(v));
    return d;
}
__device__ __forceinline__ ull packf2(float lo, float hi) {
    ull d;
    asm("mov.b64 %0, {%1, %2};" : "=l"(d) : "f"(lo), "f"(hi));
    return d;
}
__device__ __forceinline__ float tanhx(float v) {
    float r; asm("tanh.approx.f32 %0, %1;" : "=f"(r) : "f"(v)); return r;
}
__device__ __forceinline__ float sigx(float v) { return fmaf(tanhx(0.5f * v), 0.5f, 0.5f); }

__device__ __forceinline__ uint32_t smem_u32(const void* p) {
    uint32_t a;
    asm("{ .reg .u64 t; cvta.to.shared.u64 t, %1; cvt.u32.u64 %0, t; }" : "=r"(a) : "l"(p));
    return a;
}
__device__ __forceinline__ uint32_t ctarank() {
    uint32_t r; asm("mov.u32 %0, %%cluster_ctarank;" : "=r"(r)); return r;
}
__device__ __forceinline__ void stc64(uint32_t addr, uint32_t rank, ull v) {
    asm volatile("{ .reg .u32 ra; mapa.shared::cluster.u32 ra, %0, %1;"
                 " st.shared::cluster.b64 [ra], %2; }"
                 :: "r"(addr), "r"(rank), "l"(v) : "memory");
}
__device__ __forceinline__ void stc32(uint32_t addr, uint32_t rank, float v) {
    asm volatile("{ .reg .u32 ra; mapa.shared::cluster.u32 ra, %0, %1;"
                 " st.shared::cluster.f32 [ra], %2; }"
                 :: "r"(addr), "r"(rank), "f"(v) : "memory");
}
__device__ __forceinline__ void cl_sync() {
    asm volatile("barrier.cluster.arrive.aligned;" ::: "memory");
    asm volatile("barrier.cluster.wait.aligned;" ::: "memory");
}

// acc[jp*4+rr] += WT[k][j-quad] * h_dup[k][r-quad], k = 0..KN-1
template <int KN>
__device__ __forceinline__ void mv_dup(const float* SF, int wof, int hof,
                                       int jg, int jq, int rq, ull acc[8]) {
    const char* wp = (const char*)(SF + wof + 32 * jg + 4 * jq);
    const char* hp = (const char*)(SF + hof + 8 * rq);
#pragma unroll 8
    for (int k = 0; k < KN; k++) {
        ulonglong2 wv = *(const ulonglong2*)(wp + k * 512);
        ulonglong2 ha = *(const ulonglong2*)(hp + k * 128);
        ulonglong2 hb = *(const ulonglong2*)(hp + k * 128 + 16);
        acc[0] = ffma2(wv.x, ha.x, acc[0]);
        acc[1] = ffma2(wv.x, ha.y, acc[1]);
        acc[2] = ffma2(wv.x, hb.x, acc[2]);
        acc[3] = ffma2(wv.x, hb.y, acc[3]);
        acc[4] = ffma2(wv.y, ha.x, acc[4]);
        acc[5] = ffma2(wv.y, ha.y, acc[5]);
        acc[6] = ffma2(wv.y, hb.x, acc[6]);
        acc[7] = ffma2(wv.y, hb.y, acc[7]);
    }
}

// same but h non-duplicated (h2): replicate via mov
template <int KN>
__device__ __forceinline__ void mv_nodup(const float* SF, int wof, int hof,
                                         int jg, int jq, int rq, ull acc[8]) {
    const char* wp = (const char*)(SF + wof + 32 * jg + 4 * jq);
    const char* hp = (const char*)(SF + hof + 4 * rq);
#pragma unroll 8
    for (int k = 0; k < KN; k++) {
        ulonglong2 wv = *(const ulonglong2*)(wp + k * 512);
        float4 hv = *(const float4*)(hp + k * 64);
        ull h0 = repf(hv.x), h1 = repf(hv.y), h2 = repf(hv.z), h3 = repf(hv.w);
        acc[0] = ffma2(wv.x, h0, acc[0]);
        acc[1] = ffma2(wv.x, h1, acc[1]);
        acc[2] = ffma2(wv.x, h2, acc[2]);
        acc[3] = ffma2(wv.x, h3, acc[3]);
        acc[4] = ffma2(wv.y, h0, acc[4]);
        acc[5] = ffma2(wv.y, h1, acc[5]);
        acc[6] = ffma2(wv.y, h2, acc[6]);
        acc[7] = ffma2(wv.y, h3, acc[7]);
    }
}

__device__ __forceinline__ void gb_put(float* SF, int jg, int jq, int rq,
                                       const ull acc[8], bool addin) {
#pragma unroll
    for (int rr = 0; rr < 4; rr++)
#pragma unroll
        for (int jp = 0; jp < 2; jp++) {
            ull* p = (ull*)(SF + FGB + (4 * rq + rr) * 132 + 32 * jg + 4 * jq + 2 * jp);
            ull v = acc[jp * 4 + rr];
            *p = addin ? add2(*p, v) : v;
        }
}

__global__ void __launch_bounds__(NT, 1) __cluster_dims__(CSIZE, 1, 1)
lstm_tile(const float* __restrict__ x,
          const float* __restrict__ w_ih1, const float* __restrict__ w_hh1,
          const float* __restrict__ b_ih1, const float* __restrict__ b_hh1,
          const float* __restrict__ w_ih2, const float* __restrict__ w_hh2,
          const float* __restrict__ b_ih2, const float* __restrict__ b_hh2,
          const float* __restrict__ w_lin, const float* __restrict__ b_lin,
          float* __restrict__ out)
{
    extern __shared__ float SF[];

    const int tid  = threadIdx.x;
    const uint32_t rank = ctarank();
    const int clus = blockIdx.x >> 2;
    const int row0 = clus * RWS;
    const int UB   = rank * 32;

    const int wid  = tid >> 5;
    const int lane = tid & 31;
    const int jg = wid & 3;        // gate group (warp covers gate jg's 32 units)
    const int kh = wid >> 2;       // k-half / source selector
    const int jq = lane >> 2;      // j quad 0..7
    const int rq = lane & 3;       // r quad 0..3

    // ---- one-time: transpose weights to k-major WT[k][128j] ----
    for (int idx = tid; idx < 16384; idx += NT) {
        int j = idx >> 7, k = idx & 127;           // k fast -> coalesced LDG
        int gj = (j >> 5) * 128 + UB + (j & 31);
        SF[FW1  + k * 128 + j] = w_hh1[gj * 128 + k];
        SF[FW2I + k * 128 + j] = w_ih2[gj * 128 + k];
        SF[FW2H + k * 128 + j] = w_hh2[gj * 128 + k];
    }
    for (int i = tid; i < 128; i += NT) {
        int gj = (i >> 5) * 128 + UB + (i & 31);
        SF[FBS1 + i] = b_ih1[gj] + b_hh1[gj];
        SF[FBS2 + i] = b_ih2[gj] + b_hh2[gj];
        SF[FWI1 + i] = w_ih1[gj];
        SF[FWL + i]  = w_lin[i];
    }
    for (int i = tid; i < 4096; i += NT) SF[FH1D + i] = 0.0f;
    for (int i = tid; i < 2048; i += NT) SF[FH2 + i]  = 0.0f;

    const float blin = b_lin[0];
    const uint32_t smb = smem_u32(SF);

    // activation task mapping: thread -> unit u, row pair (2*r2, 2*r2+1)
    const int u  = tid >> 3;
    const int r2 = tid & 7;
    const int rA = 2 * r2, rB = 2 * r2 + 1;
    float c1a = 0.f, c1b = 0.f, c2a = 0.f, c2b = 0.f;

    // readout mapping: 8 threads per row
    const int ro_r = tid >> 3;           // row 0..15 (tid<128)
    const int ro_u = (tid & 7) * 16;     // unit slice base

    __syncthreads();
    cl_sync();

    for (int t = 0; t < LSEQ; t++) {
        if (tid < RWS) SF[FXS + tid] = x[(row0 + tid) * LSEQ + t];

        // ---- mv1: gates1 = h1 @ Whh1^T, k-halves across kh ----
        {
            ull acc[8] = {0, 0, 0, 0, 0, 0, 0, 0};
            mv_dup<64>(SF, FW1 + kh * 64 * 128, FH1D + kh * 64 * 32, jg, jq, rq, acc);
            if (kh == 0) gb_put(SF, jg, jq, rq, acc, false);
            __syncthreads();
            if (kh == 1) gb_put(SF, jg, jq, rq, acc, true);
            __syncthreads();
        }
        cl_sync();   // B1: all ranks finished reading h1(t-1)

        // ---- act1: c1/h1 update + cluster broadcast (dup pairs) ----
        {
            float xA = SF[FXS + rA], xB = SF[FXS + rB];
            float g0 = SF[FGB + rA * 132 + u];
            float g1 = SF[FGB + rA * 132 + 32 + u];
            float g2 = SF[FGB + rA * 132 + 64 + u];
            float g3 = SF[FGB + rA * 132 + 96 + u];
            float b0 = SF[FBS1 + u], b1 = SF[FBS1 + 32 + u];
            float b2 = SF[FBS1 + 64 + u], b3 = SF[FBS1 + 96 + u];
            float w0 = SF[FWI1 + u], w1 = SF[FWI1 + 32 + u];
            float w2 = SF[FWI1 + 64 + u], w3 = SF[FWI1 + 96 + u];
            float iv = sigx (fmaf(w0, xA, g0 + b0));
            float fv = sigx (fmaf(w1, xA, g1 + b1));
            float gv = tanhx(fmaf(w2, xA, g2 + b2));
            float ov = sigx (fmaf(w3, xA, g3 + b3));
            c1a = fmaf(fv, c1a, iv * gv);
            float hA = ov * tanhx(c1a);

            g0 = SF[FGB + rB * 132 + u];
            g1 = SF[FGB + rB * 132 + 32 + u];
            g2 = SF[FGB + rB * 132 + 64 + u];
            g3 = SF[FGB + rB * 132 + 96 + u];
            iv = sigx (fmaf(w0, xB, g0 + b0));
            fv = sigx (fmaf(w1, xB, g1 + b1));
            gv = tanhx(fmaf(w2, xB, g2 + b2));
            ov = sigx (fmaf(w3, xB, g3 + b3));
            c1b = fmaf(fv, c1b, iv * gv);
            float hB = ov * tanhx(c1b);

            ull pA = packf2(hA, hA), pB = packf2(hB, hB);
            uint32_t aA = smb + 4u * (FH1D + (UB + u) * 32 + 2 * rA);
            uint32_t aB = smb + 4u * (FH1D + (UB + u) * 32 + 2 * rB);
#pragma unroll
            for (int rr = 0; rr < CSIZE; rr++) {
                stc64(aA, rr, pA);
                stc64(aB, rr, pB);
            }
        }
        cl_sync();   // B2: h1(t) visible cluster-wide

        // ---- mv2: gates2 = h1 @ Wih2^T + h2 @ Whh2^T (kh0: h1-dup, kh1: h2) ----
        {
            ull acc[8] = {0, 0, 0, 0, 0, 0, 0, 0};
            if (kh == 0) {
                mv_dup<128>(SF, FW2I, FH1D, jg, jq, rq, acc);
                gb_put(SF, jg, jq, rq, acc, false);
                __syncthreads();
                __syncthreads();
            } else {
                mv_nodup<128>(SF, FW2H, FH2, jg, jq, rq, acc);
                __syncthreads();
                gb_put(SF, jg, jq, rq, acc, true);
                __syncthreads();
            }
        }

        // ---- readout of step t-1 (reads h2(t-1)) ----
        if (t > 0 && tid < 128) {
            float s = 0.0f;
#pragma unroll
            for (int i = 0; i < 16; i++)
                s = fmaf(SF[FH2 + (ro_u + i) * 16 + ro_r], SF[FWL + ro_u + i], s);
            s += __shfl_xor_sync(0xffffffffu, s, 1);
            s += __shfl_xor_sync(0xffffffffu, s, 2);
            s += __shfl_xor_sync(0xffffffffu, s, 4);
            if ((tid & 7) == 0) out[(row0 + ro_r) * LSEQ + (t - 1)] = s + blin;
        }
        cl_sync();   // B3: all ranks done reading h2(t-1)

        // ---- act2: c2/h2 update + cluster broadcast ----
        {
            float g0 = SF[FGB + rA * 132 + u];
            float g1 = SF[FGB + rA * 132 + 32 + u];
            float g2 = SF[FGB + rA * 132 + 64 + u];
            float g3 = SF[FGB + rA * 132 + 96 + u];
            float b0 = SF[FBS2 + u], b1 = SF[FBS2 + 32 + u];
            float b2 = SF[FBS2 + 64 + u], b3 = SF[FBS2 + 96 + u];
            float iv = sigx (g0 + b0);
            float fv = sigx (g1 + b1);
            float gv = tanhx(g2 + b2);
            float ov = sigx (g3 + b3);
            c2a = fmaf(fv, c2a, iv * gv);
            float hA = ov * tanhx(c2a);

            g0 = SF[FGB + rB * 132 + u];
            g1 = SF[FGB + rB * 132 + 32 + u];
            g2 = SF[FGB + rB * 132 + 64 + u];
            g3 = SF[FGB + rB * 132 + 96 + u];
            iv = sigx (g0 + b0);
            fv = sigx (g1 + b1);
            gv = tanhx(g2 + b2);
            ov = sigx (g3 + b3);
            c2b = fmaf(fv, c2b, iv * gv);
            float hB = ov * tanhx(c2b);

            uint32_t aA = smb + 4u * (FH2 + (UB + u) * 16 + rA);
            uint32_t aB = smb + 4u * (FH2 + (UB + u) * 16 + rB);
#pragma unroll
            for (int rr = 0; rr < CSIZE; rr++) {
                stc32(aA, rr, hA);
                stc32(aB, rr, hB);
            }
        }
        __syncthreads();   // protect GB/XS before next step
    }

    // final readout: h2(L-1)
    cl_sync();
    if (tid < 128) {
        float s = 0.0f;
#pragma unroll
        for (int i = 0; i < 16; i++)
            s = fmaf(SF[FH2 + (ro_u + i) * 16 + ro_r], SF[FWL + ro_u + i], s);
        s += __shfl_xor_sync(0xffffffffu, s, 1);
        s += __shfl_xor_sync(0xffffffffu, s, 2);
        s += __shfl_xor_sync(0xffffffffu, s, 4);
        if ((tid & 7) == 0) out[(row0 + ro_r) * LSEQ + (LSEQ - 1)] = s + blin;
    }
}

extern "C" void kernel_launch(void* const* d_in, const int* in_sizes, int n_in,
                              void* d_out, int out_size) {
    cudaFuncSetAttribute(lstm_tile, cudaFuncAttributeMaxDynamicSharedMemorySize, SMEM_SZ);

    const float* x     = (const float*)d_in[0];
    const float* w_ih1 = (const float*)d_in[1];
    const float* w_hh1 = (const float*)d_in[2];
    const float* b_ih1 = (const float*)d_in[3];
    const float* b_hh1 = (const float*)d_in[4];
    const float* w_ih2 = (const float*)d_in[5];
    const float* w_hh2 = (const float*)d_in[6];
    const float* b_ih2 = (const float*)d_in[7];
    const float* b_hh2 = (const float*)d_in[8];
    const float* w_lin = (const float*)d_in[9];
    const float* b_lin = (const float*)d_in[10];
    float* out = (float*)d_out;

    lstm_tile<<<NCTA, NT, SMEM_SZ>>>(x, w_ih1, w_hh1, b_ih1, b_hh1,
                                     w_ih2, w_hh2, b_ih2, b_hh2,
                                     w_lin, b_lin, out);
}

// round 11
// speedup vs baseline: 3.0810x; 1.7815x over previous
#include <cuda_runtime.h>
#include <cstdint>

#define CSIZE 4
#define NCTA  128
#define NT    512
#define RWS   16
#define LSEQ  1000

// float-index offsets in dynamic SMEM (identical map to R9)
#define FW1   0          // WT1 [128k][128j]
#define FW2I  16384      // WT2I
#define FW2H  32768      // WT2H
#define FH1D  49152      // h1 dup: [128k][32]  (pairs (h_r,h_r), r=0..15)
#define FH2   53248      // h2:     [128k][16]
#define FGB   55296      // gates:  [16r][132]
#define FBS1  57408      // [4][32]
#define FBS2  57536
#define FWI1  57664
#define FWL   57792      // [128]
#define FXS   57920      // [16]
#define SMEM_SZ (57936 * 4)

typedef unsigned long long ull;

__device__ __forceinline__ ull ffma2(ull a, ull b, ull c) {
    ull d;
    asm("fma.rn.f32x2 %0, %1, %2, %3;" : "=l"(d) : "l"(a), "l"(b), "l"(c));
    return d;
}
__device__ __forceinline__ ull add2(ull a, ull b) {
    ull d;
    asm("add.rn.f32x2 %0, %1, %2;" : "=l"(d) : "l"(a), "l"(b));
    return d;
}
__device__ __forceinline__ ull repf(float v) {
    ull d;
    asm("mov.b64 %0, {%1, %1};" : "=l"(d) : "f"(v));
    return d;
}
__device__ __forceinline__ ull packf2(float lo, float hi) {
    ull d;
    asm("mov.b64 %0, {%1, %2};" : "=l"(d) : "f"(lo), "f"(hi));
    return d;
}
__device__ __forceinline__ float tanhx(float v) {
    float r; asm("tanh.approx.f32 %0, %1;" : "=f"(r) : "f"(v)); return r;
}
__device__ __forceinline__ float sigx(float v) { return fmaf(tanhx(0.5f * v), 0.5f, 0.5f); }

__device__ __forceinline__ uint32_t smem_u32(const void* p) {
    uint32_t a;
    asm("{ .reg .u64 t; cvta.to.shared.u64 t, %1; cvt.u32.u64 %0, t; }" : "=r"(a) : "l"(p));
    return a;
}
__device__ __forceinline__ uint32_t ctarank() {
    uint32_t r; asm("mov.u32 %0, %%cluster_ctarank;" : "=r"(r)); return r;
}
__device__ __forceinline__ void stc64(uint32_t addr, uint32_t rank, ull v) {
    asm volatile("{ .reg .u32 ra; mapa.shared::cluster.u32 ra, %0, %1;"
                 " st.shared::cluster.b64 [ra], %2; }"
                 :: "r"(addr), "r"(rank), "l"(v) : "memory");
}
__device__ __forceinline__ void stc32(uint32_t addr, uint32_t rank, float v) {
    asm volatile("{ .reg .u32 ra; mapa.shared::cluster.u32 ra, %0, %1;"
                 " st.shared::cluster.f32 [ra], %2; }"
                 :: "r"(addr), "r"(rank), "f"(v) : "memory");
}
__device__ __forceinline__ void cl_sync() {
    asm volatile("barrier.cluster.arrive.aligned;" ::: "memory");
    asm volatile("barrier.cluster.wait.aligned;" ::: "memory");
}

// acc[jp*4+rr] += WT[k][j-quad] * h_dup[k][r-quad], k = 0..KN-1
template <int KN>
__device__ __forceinline__ void mv_dup(const float* SF, int wof, int hof,
                                       int jg, int jq, int rq, ull acc[8]) {
    const char* wp = (const char*)(SF + wof + 32 * jg + 4 * jq);
    const char* hp = (const char*)(SF + hof + 8 * rq);
#pragma unroll 8
    for (int k = 0; k < KN; k++) {
        ulonglong2 wv = *(const ulonglong2*)(wp + k * 512);
        ulonglong2 ha = *(const ulonglong2*)(hp + k * 128);
        ulonglong2 hb = *(const ulonglong2*)(hp + k * 128 + 16);
        acc[0] = ffma2(wv.x, ha.x, acc[0]);
        acc[1] = ffma2(wv.x, ha.y, acc[1]);
        acc[2] = ffma2(wv.x, hb.x, acc[2]);
        acc[3] = ffma2(wv.x, hb.y, acc[3]);
        acc[4] = ffma2(wv.y, ha.x, acc[4]);
        acc[5] = ffma2(wv.y, ha.y, acc[5]);
        acc[6] = ffma2(wv.y, hb.x, acc[6]);
        acc[7] = ffma2(wv.y, hb.y, acc[7]);
    }
}

// same but h non-duplicated (h2): replicate via mov
template <int KN>
__device__ __forceinline__ void mv_nodup(const float* SF, int wof, int hof,
                                         int jg, int jq, int rq, ull acc[8]) {
    const char* wp = (const char*)(SF + wof + 32 * jg + 4 * jq);
    const char* hp = (const char*)(SF + hof + 4 * rq);
#pragma unroll 8
    for (int k = 0; k < KN; k++) {
        ulonglong2 wv = *(const ulonglong2*)(wp + k * 512);
        float4 hv = *(const float4*)(hp + k * 64);
        ull h0 = repf(hv.x), h1 = repf(hv.y), h2 = repf(hv.z), h3 = repf(hv.w);
        acc[0] = ffma2(wv.x, h0, acc[0]);
        acc[1] = ffma2(wv.x, h1, acc[1]);
        acc[2] = ffma2(wv.x, h2, acc[2]);
        acc[3] = ffma2(wv.x, h3, acc[3]);
        acc[4] = ffma2(wv.y, h0, acc[4]);
        acc[5] = ffma2(wv.y, h1, acc[5]);
        acc[6] = ffma2(wv.y, h2, acc[6]);
        acc[7] = ffma2(wv.y, h3, acc[7]);
    }
}

__device__ __forceinline__ void gb_put(float* SF, int jg, int jq, int rq,
                                       const ull acc[8], bool addin) {
#pragma unroll
    for (int rr = 0; rr < 4; rr++)
#pragma unroll
        for (int jp = 0; jp < 2; jp++) {
            ull* p = (ull*)(SF + FGB + (4 * rq + rr) * 132 + 32 * jg + 4 * jq + 2 * jp);
            ull v = acc[jp * 4 + rr];
            *p = addin ? add2(*p, v) : v;
        }
}

__global__ void __launch_bounds__(NT, 1) __cluster_dims__(CSIZE, 1, 1)
lstm_t512(const float* __restrict__ x,
          const float* __restrict__ w_ih1, const float* __restrict__ w_hh1,
          const float* __restrict__ b_ih1, const float* __restrict__ b_hh1,
          const float* __restrict__ w_ih2, const float* __restrict__ w_hh2,
          const float* __restrict__ b_ih2, const float* __restrict__ b_hh2,
          const float* __restrict__ w_lin, const float* __restrict__ b_lin,
          float* __restrict__ out)
{
    extern __shared__ float SF[];

    const int tid  = threadIdx.x;
    const uint32_t rank = ctarank();
    const int clus = blockIdx.x >> 2;
    const int row0 = clus * RWS;
    const int UB   = rank * 32;

    const int wid  = tid >> 5;
    const int lane = tid & 31;
    const int jg  = wid & 3;       // gate group
    const int sel = wid >> 2;      // 0..3: mv1 k-quarter; mv2 (mat, k-half)
    const int jq = lane >> 2;      // j quad 0..7
    const int rq = lane & 3;       // r quad 0..3

    // mv1: k-quarter bases
    const int w1of = FW1 + 32 * sel * 128;
    const int h1of = FH1D + 32 * sel * 32;
    // mv2: mat = sel&1 (0: W2I x h1dup, 1: W2H x h2), kh = sel>>1
    const int mat = sel & 1, kh2 = sel >> 1;
    const int w2of = (mat ? FW2H : FW2I) + 64 * kh2 * 128;
    const int h2of = mat ? (FH2 + 64 * kh2 * 16) : (FH1D + 64 * kh2 * 32);

    // ---- one-time: transpose weights to k-major WT[k][128j] ----
    for (int idx = tid; idx < 16384; idx += NT) {
        int j = idx >> 7, k = idx & 127;           // k fast -> coalesced LDG
        int gj = (j >> 5) * 128 + UB + (j & 31);
        SF[FW1  + k * 128 + j] = w_hh1[gj * 128 + k];
        SF[FW2I + k * 128 + j] = w_ih2[gj * 128 + k];
        SF[FW2H + k * 128 + j] = w_hh2[gj * 128 + k];
    }
    for (int i = tid; i < 128; i += NT) {
        int gj = (i >> 5) * 128 + UB + (i & 31);
        SF[FBS1 + i] = b_ih1[gj] + b_hh1[gj];
        SF[FBS2 + i] = b_ih2[gj] + b_hh2[gj];
        SF[FWI1 + i] = w_ih1[gj];
        SF[FWL + i]  = w_lin[i];
    }
    for (int i = tid; i < 4096; i += NT) SF[FH1D + i] = 0.0f;
    for (int i = tid; i < 2048; i += NT) SF[FH2 + i]  = 0.0f;

    const float blin = b_lin[0];
    const uint32_t smb = smem_u32(SF);

    // activation task mapping: one (unit, row) per thread
    const int u = tid >> 4;        // 0..31
    const int r = tid & 15;        // 0..15
    float c1 = 0.f, c2 = 0.f;

    // readout mapping: 8 threads per row (tid < 128)
    const int ro_r = tid >> 3;
    const int ro_u = (tid & 7) * 16;

    __syncthreads();
    cl_sync();

    for (int t = 0; t < LSEQ; t++) {
        if (tid < RWS) SF[FXS + tid] = x[(row0 + tid) * LSEQ + t];

        // ---- mv1: gates1 = h1 @ Whh1^T, 4 k-quarters merged in waves ----
        {
            ull acc[8] = {0, 0, 0, 0, 0, 0, 0, 0};
            mv_dup<32>(SF, w1of, h1of, jg, jq, rq, acc);
            if (sel == 0) gb_put(SF, jg, jq, rq, acc, false);
            __syncthreads();
            if (sel == 1) gb_put(SF, jg, jq, rq, acc, true);
            __syncthreads();
            if (sel == 2) gb_put(SF, jg, jq, rq, acc, true);
            __syncthreads();
            if (sel == 3) gb_put(SF, jg, jq, rq, acc, true);
        }
        cl_sync();   // B1: GB complete; all ranks finished reading h1(t-1)

        // ---- act1: c1/h1 update + cluster broadcast (dup pairs) ----
        {
            float xr = SF[FXS + r];
            float g0 = SF[FGB + r * 132 + u];
            float g1 = SF[FGB + r * 132 + 32 + u];
            float g2 = SF[FGB + r * 132 + 64 + u];
            float g3 = SF[FGB + r * 132 + 96 + u];
            float iv = sigx (fmaf(SF[FWI1 + u],      xr, g0 + SF[FBS1 + u]));
            float fv = sigx (fmaf(SF[FWI1 + 32 + u], xr, g1 + SF[FBS1 + 32 + u]));
            float gv = tanhx(fmaf(SF[FWI1 + 64 + u], xr, g2 + SF[FBS1 + 64 + u]));
            float ov = sigx (fmaf(SF[FWI1 + 96 + u], xr, g3 + SF[FBS1 + 96 + u]));
            c1 = fmaf(fv, c1, iv * gv);
            float h = ov * tanhx(c1);
            ull ph = packf2(h, h);
            uint32_t ad = smb + 4u * (FH1D + (UB + u) * 32 + 2 * r);
#pragma unroll
            for (int rr = 0; rr < CSIZE; rr++) stc64(ad, rr, ph);
        }
        cl_sync();   // B2: h1(t) visible cluster-wide

        // ---- mv2: gates2 = h1 @ Wih2^T + h2 @ Whh2^T, 4 partials in waves ----
        {
            ull acc[8] = {0, 0, 0, 0, 0, 0, 0, 0};
            if (mat == 0) mv_dup<64>(SF, w2of, h2of, jg, jq, rq, acc);
            else          mv_nodup<64>(SF, w2of, h2of, jg, jq, rq, acc);
            if (sel == 0) gb_put(SF, jg, jq, rq, acc, false);
            __syncthreads();
            if (sel == 1) gb_put(SF, jg, jq, rq, acc, true);
            __syncthreads();
            if (sel == 2) gb_put(SF, jg, jq, rq, acc, true);
            __syncthreads();
            if (sel == 3) gb_put(SF, jg, jq, rq, acc, true);
            __syncthreads();
        }

        // ---- readout of step t-1 (reads h2(t-1)) ----
        if (t > 0 && tid < 128) {
            float s = 0.0f;
#pragma unroll
            for (int i = 0; i < 16; i++)
                s = fmaf(SF[FH2 + (ro_u + i) * 16 + ro_r], SF[FWL + ro_u + i], s);
            s += __shfl_xor_sync(0xffffffffu, s, 1);
            s += __shfl_xor_sync(0xffffffffu, s, 2);
            s += __shfl_xor_sync(0xffffffffu, s, 4);
            if ((tid & 7) == 0) out[(row0 + ro_r) * LSEQ + (t - 1)] = s + blin;
        }
        cl_sync();   // B3: all ranks done reading h2(t-1); GB stable for act2

        // ---- act2: c2/h2 update + cluster broadcast ----
        {
            float g0 = SF[FGB + r * 132 + u];
            float g1 = SF[FGB + r * 132 + 32 + u];
            float g2 = SF[FGB + r * 132 + 64 + u];
            float g3 = SF[FGB + r * 132 + 96 + u];
            float iv = sigx (g0 + SF[FBS2 + u]);
            float fv = sigx (g1 + SF[FBS2 + 32 + u]);
            float gv = tanhx(g2 + SF[FBS2 + 64 + u]);
            float ov = sigx (g3 + SF[FBS2 + 96 + u]);
            c2 = fmaf(fv, c2, iv * gv);
            float h = ov * tanhx(c2);
            uint32_t ad = smb + 4u * (FH2 + (UB + u) * 16 + r);
#pragma unroll
            for (int rr = 0; rr < CSIZE; rr++) stc32(ad, rr, h);
        }
        __syncthreads();   // protect GB/XS before next step
    }

    // final readout: h2(L-1)
    cl_sync();
    if (tid < 128) {
        float s = 0.0f;
#pragma unroll
        for (int i = 0; i < 16; i++)
            s = fmaf(SF[FH2 + (ro_u + i) * 16 + ro_r], SF[FWL + ro_u + i], s);
        s += __shfl_xor_sync(0xffffffffu, s, 1);
        s += __shfl_xor_sync(0xffffffffu, s, 2);
        s += __shfl_xor_sync(0xffffffffu, s, 4);
        if ((tid & 7) == 0) out[(row0 + ro_r) * LSEQ + (LSEQ - 1)] = s + blin;
    }
}

extern "C" void kernel_launch(void* const* d_in, const int* in_sizes, int n_in,
                              void* d_out, int out_size) {
    cudaFuncSetAttribute(lstm_t512, cudaFuncAttributeMaxDynamicSharedMemorySize, SMEM_SZ);

    const float* x     = (const float*)d_in[0];
    const float* w_ih1 = (const float*)d_in[1];
    const float* w_hh1 = (const float*)d_in[2];
    const float* b_ih1 = (const float*)d_in[3];
    const float* b_hh1 = (const float*)d_in[4];
    const float* w_ih2 = (const float*)d_in[5];
    const float* w_hh2 = (const float*)d_in[6];
    const float* b_ih2 = (const float*)d_in[7];
    const float* b_hh2 = (const float*)d_in[8];
    const float* w_lin = (const float*)d_in[9];
    const float* b_lin = (const float*)d_in[10];
    float* out = (float*)d_out;

    lstm_t512<<<NCTA, NT, SMEM_SZ>>>(x, w_ih1, w_hh1, b_ih1, b_hh1,
                                     w_ih2, w_hh2, b_ih2, b_hh2,
                                     w_lin, b_lin, out);
}